// round 1
// baseline (speedup 1.0000x reference)
#include <cuda_runtime.h>
#include <cstdint>

// PSRoIAlign: feat [B=4, C=784, H=80, W=80] fp32, rois [512,5] fp32
// out [512, 16, 7, 7] fp32.  C layout = (Co=16, PH=7, PW=7), so channel
// index == intra-ROI output index (co*49 + i*7 + j).

#define B_    4
#define CO_   16
#define PH_   7
#define PW_   7
#define H_    80
#define W_    80
#define SR_   2
#define C_    (CO_ * PH_ * PW_)   // 784
#define HW_   (H_ * W_)           // 6400

__global__ __launch_bounds__(C_, 2)
void psroi_align_kernel(const float* __restrict__ feat,
                        const float* __restrict__ rois,
                        float* __restrict__ out)
{
    const int n   = blockIdx.x;     // roi index
    const int tid = threadIdx.x;    // 0..783 == channel c == output index in roi

    __shared__ float r[5];
    if (tid < 5) r[tid] = rois[n * 5 + tid];
    __syncthreads();

    const int   b  = (int)r[0];
    const float x1 = r[1] * (float)W_;
    const float y1 = r[2] * (float)H_;
    const float x2 = r[3] * (float)W_;
    const float y2 = r[4] * (float)H_;

    const float roi_h = fmaxf(y2 - y1, 0.1f);
    const float roi_w = fmaxf(x2 - x1, 0.1f);
    const float bin_h = roi_h / (float)PH_;
    const float bin_w = roi_w / (float)PW_;

    const int j = tid % PW_;
    const int i = (tid / PW_) % PH_;

    const float* __restrict__ f = feat + ((size_t)b * C_ + tid) * HW_;

    // --- per-thread sample coords: 2 y-samples, 2 x-samples ---
    int   y0i[SR_], y1i[SR_], x0i[SR_], x1i[SR_];
    float hy[SR_], ly[SR_], hx[SR_], lx[SR_];
    bool  ym[SR_], xm[SR_];

    #pragma unroll
    for (int s = 0; s < SR_; s++) {
        float ys = y1 + (float)i * bin_h + ((float)s + 0.5f) * bin_h / (float)SR_;
        ym[s] = (ys >= -1.0f) && (ys <= (float)H_);
        float yc = fminf(fmaxf(ys, 0.0f), (float)(H_ - 1));
        float yf = floorf(yc);
        y0i[s] = (int)yf;
        y1i[s] = min(y0i[s] + 1, H_ - 1);
        ly[s]  = yc - yf;
        hy[s]  = 1.0f - ly[s];

        float xs = x1 + (float)j * bin_w + ((float)s + 0.5f) * bin_w / (float)SR_;
        xm[s] = (xs >= -1.0f) && (xs <= (float)W_);
        float xc = fminf(fmaxf(xs, 0.0f), (float)(W_ - 1));
        float xf = floorf(xc);
        x0i[s] = (int)xf;
        x1i[s] = min(x0i[s] + 1, W_ - 1);
        lx[s]  = xc - xf;
        hx[s]  = 1.0f - lx[s];
    }

    // --- front-batch all 16 gathers for maximum MLP ---
    float v00[SR_][SR_], v01[SR_][SR_], v10[SR_][SR_], v11[SR_][SR_];
    #pragma unroll
    for (int sy = 0; sy < SR_; sy++) {
        const float* row0 = f + y0i[sy] * W_;
        const float* row1 = f + y1i[sy] * W_;
        #pragma unroll
        for (int sx = 0; sx < SR_; sx++) {
            v00[sy][sx] = __ldg(row0 + x0i[sx]);
            v01[sy][sx] = __ldg(row0 + x1i[sx]);
            v10[sy][sx] = __ldg(row1 + x0i[sx]);
            v11[sy][sx] = __ldg(row1 + x1i[sx]);
        }
    }

    float sum = 0.0f;
    #pragma unroll
    for (int sy = 0; sy < SR_; sy++) {
        #pragma unroll
        for (int sx = 0; sx < SR_; sx++) {
            float v = hy[sy] * (hx[sx] * v00[sy][sx] + lx[sx] * v01[sy][sx])
                    + ly[sy] * (hx[sx] * v10[sy][sx] + lx[sx] * v11[sy][sx]);
            if (ym[sy] && xm[sx]) sum += v;
        }
    }

    out[(size_t)n * C_ + tid] = sum * (1.0f / (float)(SR_ * SR_));
}

extern "C" void kernel_launch(void* const* d_in, const int* in_sizes, int n_in,
                              void* d_out, int out_size)
{
    const float* feat = (const float*)d_in[0];
    const float* rois = (const float*)d_in[1];
    float* out        = (float*)d_out;

    const int n_rois = in_sizes[1] / 5;   // 512
    psroi_align_kernel<<<n_rois, C_>>>(feat, rois, out);
}

// round 2
// speedup vs baseline: 1.2739x; 1.2739x over previous
#include <cuda_runtime.h>
#include <cstdint>

// PSRoIAlign: feat [B=4, C=784, H=80, W=80] fp32, rois [512,5] fp32
// out [512, 16, 7, 7] fp32.  Channel index == intra-ROI output index.
//
// Key optimization: the 4 x-positions needed per sample row span <= 4
// consecutive columns, so 2 aligned float4 loads (8-col window) replace
// 4 scalar gathers.  Divergent LDG cost ~ distinct lines touched, which
// is 32 either way, so halving the LDG count halves L1tex wavefront work.

#define B_    4
#define CO_   16
#define PH_   7
#define PW_   7
#define H_    80
#define W_    80
#define SR_   2
#define C_    (CO_ * PH_ * PW_)     // 784
#define HW_   (H_ * W_)             // 6400
#define NROI  512
#define NTOT  (NROI * C_)           // 401408
#define FEAT_ELEMS (B_ * C_ * HW_)  // 20070400
#define TPB   256

__global__ __launch_bounds__(TPB, 4)
void psroi_align_kernel(const float* __restrict__ feat,
                        const float* __restrict__ rois,
                        float* __restrict__ out)
{
    const int flat = blockIdx.x * TPB + threadIdx.x;   // grid sized exactly
    const int n = flat / C_;
    const int c = flat - n * C_;
    const int j = c % PW_;
    const int i = (c / PW_) % PH_;

    const float* __restrict__ r = rois + n * 5;
    const int   b  = (int)__ldg(r + 0);
    const float x1 = __ldg(r + 1) * (float)W_;
    const float y1 = __ldg(r + 2) * (float)H_;
    const float x2 = __ldg(r + 3) * (float)W_;
    const float y2 = __ldg(r + 4) * (float)H_;

    const float bin_h = fmaxf(y2 - y1, 0.1f) * (1.0f / (float)PH_);
    const float bin_w = fmaxf(x2 - x1, 0.1f) * (1.0f / (float)PW_);

    // ---- sample coordinates: 2 y-samples, 2 x-samples ----
    int   y0i[SR_], y1i[SR_], x0i[SR_], x1i[SR_];
    float hy[SR_], ly[SR_], hx[SR_], lx[SR_];

    #pragma unroll
    for (int s = 0; s < SR_; s++) {
        float ys = y1 + (float)i * bin_h + ((float)s + 0.5f) * bin_h * (1.0f / (float)SR_);
        bool ym = (ys >= -1.0f) && (ys <= (float)H_);
        float yc = fminf(fmaxf(ys, 0.0f), (float)(H_ - 1));
        float yf = floorf(yc);
        y0i[s] = (int)yf;
        y1i[s] = min(y0i[s] + 1, H_ - 1);
        ly[s]  = ym ? (yc - yf) : 0.0f;
        hy[s]  = ym ? (1.0f - (yc - yf)) : 0.0f;

        float xs = x1 + (float)j * bin_w + ((float)s + 0.5f) * bin_w * (1.0f / (float)SR_);
        bool xm = (xs >= -1.0f) && (xs <= (float)W_);
        float xc = fminf(fmaxf(xs, 0.0f), (float)(W_ - 1));
        float xf = floorf(xc);
        x0i[s] = (int)xf;
        x1i[s] = min(x0i[s] + 1, W_ - 1);
        lx[s]  = xm ? (xc - xf) : 0.0f;
        hx[s]  = xm ? (1.0f - (xc - xf)) : 0.0f;
    }

    // ---- column window: all needed cols in [c0, c0+6], c0 = x0i[0] & ~3 ----
    const int c0 = x0i[0] & ~3;
    const int q0 = x0i[0] & 3;           // 0..3
    const int d1 = x1i[0] - x0i[0];      // 0..1
    const int d2 = x0i[1] - x0i[0];      // 0..2
    const int d3 = x1i[1] - x0i[0];      // 0..3

    const bool pb1  = (q0 & 1) != 0;
    const bool pb2  = (q0 & 2) != 0;
    const bool pd1  = d1 != 0;
    const bool pd2a = d2 >= 1;
    const bool pd2b = d2 == 2;
    const bool p3lo = (d3 & 1) != 0;
    const bool p3hi = (d3 & 2) != 0;

    const float* __restrict__ plane = feat + ((size_t)b * C_ + c) * HW_;
    const float4* fend = (const float4*)(feat + FEAT_ELEMS) - 1;  // last valid f4

    const int rr0 = y0i[0], rr1 = y1i[0], rr2 = y0i[1], rr3 = y1i[1];

    // ---- front-batch 8 LDG.128 (max MLP) ----
    float4 lo[4], hi[4];
    {
        const float4* p0 = (const float4*)(plane + rr0 * W_ + c0);
        const float4* p1 = (const float4*)(plane + rr1 * W_ + c0);
        const float4* p2 = (const float4*)(plane + rr2 * W_ + c0);
        const float4* p3 = (const float4*)(plane + rr3 * W_ + c0);
        const float4* h0 = p0 + 1; if (h0 > fend) h0 = fend;
        const float4* h1 = p1 + 1; if (h1 > fend) h1 = fend;
        const float4* h2 = p2 + 1; if (h2 > fend) h2 = fend;
        const float4* h3 = p3 + 1; if (h3 > fend) h3 = fend;
        lo[0] = __ldg(p0); hi[0] = __ldg(h0);
        lo[1] = __ldg(p1); hi[1] = __ldg(h1);
        lo[2] = __ldg(p2); hi[2] = __ldg(h2);
        lo[3] = __ldg(p3); hi[3] = __ldg(h3);
    }

    // per-row y weight: rows are (y0[0], y1[0], y0[1], y1[1])
    const float wy[4] = { hy[0], ly[0], hy[1], ly[1] };

    float sum = 0.0f;
    #pragma unroll
    for (int k = 0; k < 4; k++) {
        const float w0 = lo[k].x, w1 = lo[k].y, w2 = lo[k].z, w3 = lo[k].w;
        const float w4 = hi[k].x, w5 = hi[k].y, w6 = hi[k].z;

        // sliding 4-window s[m] = w[q0+m]
        const float t0 = pb1 ? w1 : w0;
        const float t1 = pb1 ? w2 : w1;
        const float t2 = pb1 ? w3 : w2;
        const float t3 = pb1 ? w4 : w3;
        const float t4 = pb1 ? w5 : w4;
        const float t5 = pb1 ? w6 : w5;
        const float s0 = pb2 ? t2 : t0;
        const float s1 = pb2 ? t3 : t1;
        const float s2 = pb2 ? t4 : t2;
        const float s3 = pb2 ? t5 : t3;

        const float v0 = s0;                                   // col x0i[0]
        const float v1 = pd1 ? s1 : s0;                        // col x1i[0]
        const float v2 = pd2b ? s2 : (pd2a ? s1 : s0);         // col x0i[1]
        const float u0 = p3lo ? s1 : s0;
        const float u1 = p3lo ? s3 : s2;
        const float v3 = p3hi ? u1 : u0;                       // col x1i[1]

        sum += wy[k] * ((hx[0] * v0 + lx[0] * v1) + (hx[1] * v2 + lx[1] * v3));
    }

    out[flat] = sum * (1.0f / (float)(SR_ * SR_));
}

extern "C" void kernel_launch(void* const* d_in, const int* in_sizes, int n_in,
                              void* d_out, int out_size)
{
    const float* feat = (const float*)d_in[0];
    const float* rois = (const float*)d_in[1];
    float* out        = (float*)d_out;

    psroi_align_kernel<<<NTOT / TPB, TPB>>>(feat, rois, out);
}

// round 4
// speedup vs baseline: 1.2959x; 1.0173x over previous
#include <cuda_runtime.h>
#include <cstdint>

// PSRoIAlign: feat [B=4, C=784, H=80, W=80] fp32, rois [512,5] fp32
// out [512, 16, 7, 7] fp32.  Channel index == intra-ROI output index.
//
// R3: predicated load elision.  The kernel is L1tex line-wavefront bound
// (every lane owns its own 25KB plane -> 32 lines per divergent LDG).
// Cut per-thread line visits from 8 to ~4.5:
//   - hi float4 loaded only when the needed column window crosses into it
//   - duplicate y-rows (dy==0 / dy==1) reuse already-loaded float4s

#define B_    4
#define CO_   16
#define PH_   7
#define PW_   7
#define H_    80
#define W_    80
#define SR_   2
#define C_    (CO_ * PH_ * PW_)     // 784
#define HW_   (H_ * W_)             // 6400
#define NROI  512
#define NTOT  (NROI * C_)           // 401408
#define FEAT_ELEMS (B_ * C_ * HW_)  // 20070400
#define TPB   256

__global__ __launch_bounds__(TPB, 4)
void psroi_align_kernel(const float* __restrict__ feat,
                        const float* __restrict__ rois,
                        float* __restrict__ out)
{
    const int flat = blockIdx.x * TPB + threadIdx.x;
    const int n = flat / C_;
    const int c = flat - n * C_;
    const int j = c % PW_;
    const int i = (c / PW_) % PH_;

    const float* __restrict__ r = rois + n * 5;
    const int   b  = (int)__ldg(r + 0);
    const float x1 = __ldg(r + 1) * (float)W_;
    const float y1 = __ldg(r + 2) * (float)H_;
    const float x2 = __ldg(r + 3) * (float)W_;
    const float y2 = __ldg(r + 4) * (float)H_;

    const float bin_h = fmaxf(y2 - y1, 0.1f) * (1.0f / (float)PH_);
    const float bin_w = fmaxf(x2 - x1, 0.1f) * (1.0f / (float)PW_);

    int   y0i[SR_], y1i[SR_], x0i[SR_], x1i[SR_];
    float hy[SR_], ly[SR_], hx[SR_], lx[SR_];

    #pragma unroll
    for (int s = 0; s < SR_; s++) {
        float ys = y1 + (float)i * bin_h + ((float)s + 0.5f) * bin_h * (1.0f / (float)SR_);
        bool ym = (ys >= -1.0f) && (ys <= (float)H_);
        float yc = fminf(fmaxf(ys, 0.0f), (float)(H_ - 1));
        float yf = floorf(yc);
        y0i[s] = (int)yf;
        y1i[s] = min(y0i[s] + 1, H_ - 1);
        ly[s]  = ym ? (yc - yf) : 0.0f;
        hy[s]  = ym ? (1.0f - (yc - yf)) : 0.0f;

        float xs = x1 + (float)j * bin_w + ((float)s + 0.5f) * bin_w * (1.0f / (float)SR_);
        bool xm = (xs >= -1.0f) && (xs <= (float)W_);
        float xc = fminf(fmaxf(xs, 0.0f), (float)(W_ - 1));
        float xf = floorf(xc);
        x0i[s] = (int)xf;
        x1i[s] = min(x0i[s] + 1, W_ - 1);
        lx[s]  = xm ? (xc - xf) : 0.0f;
        hx[s]  = xm ? (1.0f - (xc - xf)) : 0.0f;
    }

    // ---- column window: needed cols = [x0, x0+d3], d3 <= 3 ----
    const int c0 = x0i[0] & ~3;
    const int q0 = x0i[0] & 3;           // 0..3
    const int d1 = x1i[0] - x0i[0];      // 0..1
    const int d2 = x0i[1] - x0i[0];      // 0..2
    const int d3 = x1i[1] - x0i[0];      // 0..3

    const bool need_hi = (q0 + d3) >= 4; // second float4 actually needed?

    const bool pb1  = (q0 & 1) != 0;
    const bool pb2  = (q0 & 2) != 0;
    const bool pd1  = d1 != 0;
    const bool pd2a = d2 >= 1;
    const bool pd2b = d2 == 2;
    const bool p3lo = (d3 & 1) != 0;
    const bool p3hi = (d3 & 2) != 0;

    const float* __restrict__ plane = feat + ((size_t)b * C_ + c) * HW_;
    const float4* fend = (const float4*)(feat + FEAT_ELEMS) - 1;

    // ---- rows: dy = y0[1]-y0[0] in {0,1,2}; dedup duplicate rows ----
    const int rr0 = y0i[0];
    const int rr1 = y1i[0];              // rr0+1 (clamped)
    const int rr2 = y0i[1];
    const int rr3 = y1i[1];              // rr2+1 (clamped)
    const int dy  = rr2 - rr0;           // 0,1,2
    const bool ld2 = (dy == 2);          // row2 is new
    const bool ld3 = (dy >= 1);          // row3 is new

    const float4* p0 = (const float4*)(plane + rr0 * W_ + c0);
    const float4* p1 = (const float4*)(plane + rr1 * W_ + c0);
    const float4* p2 = (const float4*)(plane + rr2 * W_ + c0);
    const float4* p3 = (const float4*)(plane + rr3 * W_ + c0);
    const float4* h0 = p0 + 1; if (h0 > fend) h0 = fend;
    const float4* h1 = p1 + 1; if (h1 > fend) h1 = fend;
    const float4* h2 = p2 + 1; if (h2 > fend) h2 = fend;
    const float4* h3 = p3 + 1; if (h3 > fend) h3 = fend;

    // ---- predicated front-batched loads ----
    float4 lo0 = __ldg(p0);
    float4 lo1 = __ldg(p1);
    float4 lo2 = lo0, lo3 = lo1;
    if (ld2) lo2 = __ldg(p2);
    if (ld3) { if (!ld2) lo2 = lo1; lo3 = __ldg(p3); }

    float4 hi0 = lo0, hi1 = lo1, hi2, hi3;
    if (need_hi) { hi0 = __ldg(h0); hi1 = __ldg(h1); }
    hi2 = hi0; hi3 = hi1;
    if (need_hi && ld2) hi2 = __ldg(h2);
    if (need_hi && ld3) { if (!ld2) hi2 = hi1; hi3 = __ldg(h3); }

    const float4 LO[4] = { lo0, lo1, lo2, lo3 };
    const float4 HI[4] = { hi0, hi1, hi2, hi3 };
    const float  wy[4] = { hy[0], ly[0], hy[1], ly[1] };

    float sum = 0.0f;
    #pragma unroll
    for (int k = 0; k < 4; k++) {
        const float w0 = LO[k].x, w1 = LO[k].y, w2 = LO[k].z, w3 = LO[k].w;
        const float w4 = HI[k].x, w5 = HI[k].y, w6 = HI[k].z;

        // sliding 4-window s[m] = w[q0+m]; only s[m], m<=d3 are ever selected
        const float t0 = pb1 ? w1 : w0;
        const float t1 = pb1 ? w2 : w1;
        const float t2 = pb1 ? w3 : w2;
        const float t3 = pb1 ? w4 : w3;
        const float t4 = pb1 ? w5 : w4;
        const float t5 = pb1 ? w6 : w5;
        const float s0 = pb2 ? t2 : t0;
        const float s1 = pb2 ? t3 : t1;
        const float s2 = pb2 ? t4 : t2;
        const float s3 = pb2 ? t5 : t3;

        const float v0 = s0;                               // col x0i[0]
        const float v1 = pd1 ? s1 : s0;                    // col x1i[0]
        const float v2 = pd2b ? s2 : (pd2a ? s1 : s0);     // col x0i[1]
        const float u0 = p3lo ? s1 : s0;
        const float u1 = p3lo ? s3 : s2;
        const float v3 = p3hi ? u1 : u0;                   // col x1i[1]

        sum += wy[k] * ((hx[0] * v0 + lx[0] * v1) + (hx[1] * v2 + lx[1] * v3));
    }

    out[flat] = sum * (1.0f / (float)(SR_ * SR_));
}

extern "C" void kernel_launch(void* const* d_in, const int* in_sizes, int n_in,
                              void* d_out, int out_size)
{
    const float* feat = (const float*)d_in[0];
    const float* rois = (const float*)d_in[1];
    float* out        = (float*)d_out;

    psroi_align_kernel<<<NTOT / TPB, TPB>>>(feat, rois, out);
}

// round 6
// speedup vs baseline: 1.5000x; 1.1575x over previous
#include <cuda_runtime.h>
#include <cstdint>

// PSRoIAlign: feat [B=4, C=784, H=80, W=80] fp32, rois [512,5] fp32
// out [512, 16, 7, 7] fp32.  Channel index == intra-ROI output index.
//
// R5: same load-elision plan as R3 (hi-float4 only when the column window
// crosses 16B; dedup duplicate y-rows), but in straight-line predicated
// form (single-statement conditional loads -> @P LDG, no BSSY/BSYNC),
// no bounds clamp (predicated-off LDG never touches its address; when the
// predicate is on, the address is provably in-bounds), and a 5-block
// launch bound for ~62% occupancy.

#define B_    4
#define CO_   16
#define PH_   7
#define PW_   7
#define H_    80
#define W_    80
#define SR_   2
#define C_    (CO_ * PH_ * PW_)     // 784
#define HW_   (H_ * W_)             // 6400
#define NROI  512
#define NTOT  (NROI * C_)           // 401408
#define TPB   256

__global__ __launch_bounds__(TPB, 5)
void psroi_align_kernel(const float* __restrict__ feat,
                        const float* __restrict__ rois,
                        float* __restrict__ out)
{
    const int flat = blockIdx.x * TPB + threadIdx.x;
    const int n = flat / C_;
    const int c = flat - n * C_;
    const int j = c % PW_;
    const int i = (c / PW_) % PH_;

    const float* __restrict__ r = rois + n * 5;
    const int   b  = (int)__ldg(r + 0);
    const float x1 = __ldg(r + 1) * (float)W_;
    const float y1 = __ldg(r + 2) * (float)H_;
    const float x2 = __ldg(r + 3) * (float)W_;
    const float y2 = __ldg(r + 4) * (float)H_;

    const float bin_h = fmaxf(y2 - y1, 0.1f) * (1.0f / (float)PH_);
    const float bin_w = fmaxf(x2 - x1, 0.1f) * (1.0f / (float)PW_);

    int   y0i[SR_], y1i[SR_], x0i[SR_], x1i[SR_];
    float hy[SR_], ly[SR_], hx[SR_], lx[SR_];

    #pragma unroll
    for (int s = 0; s < SR_; s++) {
        float ys = y1 + (float)i * bin_h + ((float)s + 0.5f) * bin_h * (1.0f / (float)SR_);
        bool ym = (ys >= -1.0f) && (ys <= (float)H_);
        float yc = fminf(fmaxf(ys, 0.0f), (float)(H_ - 1));
        float yf = floorf(yc);
        y0i[s] = (int)yf;
        y1i[s] = min(y0i[s] + 1, H_ - 1);
        ly[s]  = ym ? (yc - yf) : 0.0f;
        hy[s]  = ym ? (1.0f - (yc - yf)) : 0.0f;

        float xs = x1 + (float)j * bin_w + ((float)s + 0.5f) * bin_w * (1.0f / (float)SR_);
        bool xm = (xs >= -1.0f) && (xs <= (float)W_);
        float xc = fminf(fmaxf(xs, 0.0f), (float)(W_ - 1));
        float xf = floorf(xc);
        x0i[s] = (int)xf;
        x1i[s] = min(x0i[s] + 1, W_ - 1);
        lx[s]  = xm ? (xc - xf) : 0.0f;
        hx[s]  = xm ? (1.0f - (xc - xf)) : 0.0f;
    }

    // ---- column window: needed cols = [x0, x0+d3], d3 <= 3 ----
    const int c0 = x0i[0] & ~3;
    const int q0 = x0i[0] & 3;           // 0..3
    const int d1 = x1i[0] - x0i[0];      // 0..1
    const int d2 = x0i[1] - x0i[0];      // 0..2
    const int d3 = x1i[1] - x0i[0];      // 0..3

    // hi float4 needed iff window crosses the 16B boundary.  When true,
    // max needed col = c0+q0+d3 <= 79 implies c0+7 <= 79, so the hi load
    // is in-bounds whenever its predicate is on.
    const bool need_hi = (q0 + d3) >= 4;

    const bool pb1  = (q0 & 1) != 0;
    const bool pb2  = (q0 & 2) != 0;
    const bool pd1  = d1 != 0;
    const bool pd2a = d2 >= 1;
    const bool pd2b = d2 == 2;
    const bool p3lo = (d3 & 1) != 0;
    const bool p3hi = (d3 & 2) != 0;

    // ---- rows: dy = y0[1]-y0[0] in {0,1,2}; dedup duplicate rows ----
    const int dy  = y0i[1] - y0i[0];
    const bool ld2 = (dy == 2);          // row2 distinct from rows 0,1
    const bool ld3 = (dy >= 1);          // row3 distinct from rows 0,1
    const bool nh2 = need_hi && ld2;
    const bool nh3 = need_hi && ld3;

    const float* __restrict__ base = feat + ((size_t)b * C_ + c) * HW_ + c0;
    const float4* a0 = (const float4*)(base + y0i[0] * W_);
    const float4* a1 = (const float4*)(base + y1i[0] * W_);
    const float4* a2 = (const float4*)(base + y0i[1] * W_);
    const float4* a3 = (const float4*)(base + y1i[1] * W_);

    // ---- predicated front-batched loads (no branches) ----
    float4 lo0 = __ldg(a0);
    float4 lo1 = __ldg(a1);
    float4 lo2 = lo0, lo3 = lo1;
    float4 hi0 = make_float4(0.f, 0.f, 0.f, 0.f);
    float4 hi1 = hi0, hi2 = hi0, hi3 = hi0;

    if (ld2)     lo2 = __ldg(a2);
    if (ld3)     lo3 = __ldg(a3);
    if (need_hi) hi0 = __ldg(a0 + 1);
    if (need_hi) hi1 = __ldg(a1 + 1);
    if (nh2)     hi2 = __ldg(a2 + 1);
    if (nh3)     hi3 = __ldg(a3 + 1);

    // fixups for duplicated rows (pure selects)
    if (!ld2) lo2 = ld3 ? lo1 : lo0;
    if (!ld3) lo3 = lo1;
    if (!ld2) hi2 = ld3 ? hi1 : hi0;
    if (!ld3) hi3 = hi1;

    const float4 LO[4] = { lo0, lo1, lo2, lo3 };
    const float4 HI[4] = { hi0, hi1, hi2, hi3 };
    const float  wy[4] = { hy[0], ly[0], hy[1], ly[1] };

    float sum = 0.0f;
    #pragma unroll
    for (int k = 0; k < 4; k++) {
        const float w0 = LO[k].x, w1 = LO[k].y, w2 = LO[k].z, w3 = LO[k].w;
        const float w4 = HI[k].x, w5 = HI[k].y, w6 = HI[k].z;

        // sliding 4-window s[m] = w[q0+m]; only s[m], m<=d3 are ever selected
        const float t0 = pb1 ? w1 : w0;
        const float t1 = pb1 ? w2 : w1;
        const float t2 = pb1 ? w3 : w2;
        const float t3 = pb1 ? w4 : w3;
        const float t4 = pb1 ? w5 : w4;
        const float t5 = pb1 ? w6 : w5;
        const float s0 = pb2 ? t2 : t0;
        const float s1 = pb2 ? t3 : t1;
        const float s2 = pb2 ? t4 : t2;
        const float s3 = pb2 ? t5 : t3;

        const float v0 = s0;                               // col x0i[0]
        const float v1 = pd1 ? s1 : s0;                    // col x1i[0]
        const float v2 = pd2b ? s2 : (pd2a ? s1 : s0);     // col x0i[1]
        const float u0 = p3lo ? s1 : s0;
        const float u1 = p3lo ? s3 : s2;
        const float v3 = p3hi ? u1 : u0;                   // col x1i[1]

        sum += wy[k] * ((hx[0] * v0 + lx[0] * v1) + (hx[1] * v2 + lx[1] * v3));
    }

    out[flat] = sum * (1.0f / (float)(SR_ * SR_));
}

extern "C" void kernel_launch(void* const* d_in, const int* in_sizes, int n_in,
                              void* d_out, int out_size)
{
    const float* feat = (const float*)d_in[0];
    const float* rois = (const float*)d_in[1];
    float* out        = (float*)d_out;

    psroi_align_kernel<<<NTOT / TPB, TPB>>>(feat, rois, out);
}